// round 1
// baseline (speedup 1.0000x reference)
#include <cuda_runtime.h>
#include <math_constants.h>

// Problem constants
#define B_SZ   2
#define L_SEQ  2048
#define D_MOD  1024
#define NH     16
#define HD     64
#define M_ROWS (B_SZ * L_SEQ)   // 4096

// Scratch (allocation-free rule: __device__ globals)
__device__ float g_q[M_ROWS * D_MOD];
__device__ float g_k[M_ROWS * D_MOD];
__device__ float g_v[M_ROWS * D_MOD];
__device__ float g_attn[M_ROWS * D_MOD];

// ---------------------------------------------------------------------------
// Tiled SGEMM: C[M,Nc] = alpha * A[M,K] * W[K,Nc]
// BM=128, BN=128, BK=8, 8x8 microtiles, 256 threads.
// Fused QKV via blockIdx.z selecting (A, W, C, alpha).
// ---------------------------------------------------------------------------
struct GemmTriple {
    const float* A[3];
    const float* W[3];
    float*       C[3];
    float        alpha[3];
};

template <int NZ>
__global__ void __launch_bounds__(256, 2)
sgemm_kernel(GemmTriple args, int M, int Nc, int K)
{
    constexpr int BM = 128, BN = 128, BK = 8, TM = 8, TN = 8;
    __shared__ float As[BK][BM];
    __shared__ float Bs[BK][BN];

    const int z = (NZ > 1) ? blockIdx.z : 0;
    const float* __restrict__ A = args.A[z];
    const float* __restrict__ W = args.W[z];
    float* __restrict__ C = args.C[z];
    const float alpha = args.alpha[z];

    const int tid = threadIdx.x;
    const int bx = blockIdx.x, by = blockIdx.y;

    const int tx = tid % (BN / TN);   // 0..15
    const int ty = tid / (BN / TN);   // 0..15

    const float* Ab = A + (size_t)by * BM * K;
    const float* Wb = W + bx * BN;

    float acc[TM][TN];
#pragma unroll
    for (int i = 0; i < TM; ++i)
#pragma unroll
        for (int j = 0; j < TN; ++j) acc[i][j] = 0.f;

    // load indices
    const int arow = tid / (BK / 4);          // 0..127
    const int acol = (tid % (BK / 4)) * 4;    // 0 or 4
    const int brow = tid / (BN / 4);          // 0..7
    const int bcol = (tid % (BN / 4)) * 4;    // 0..124

    for (int k0 = 0; k0 < K; k0 += BK) {
        float4 a4 = *(const float4*)(Ab + (size_t)arow * K + k0 + acol);
        As[acol + 0][arow] = a4.x;
        As[acol + 1][arow] = a4.y;
        As[acol + 2][arow] = a4.z;
        As[acol + 3][arow] = a4.w;
        float4 b4 = *(const float4*)(Wb + (size_t)(k0 + brow) * Nc + bcol);
        *(float4*)(&Bs[brow][bcol]) = b4;
        __syncthreads();

#pragma unroll
        for (int kk = 0; kk < BK; ++kk) {
            float ar[TM], br[TN];
#pragma unroll
            for (int i = 0; i < TM; ++i) ar[i] = As[kk][ty * TM + i];
#pragma unroll
            for (int j = 0; j < TN; ++j) br[j] = Bs[kk][tx * TN + j];
#pragma unroll
            for (int i = 0; i < TM; ++i)
#pragma unroll
                for (int j = 0; j < TN; ++j)
                    acc[i][j] += ar[i] * br[j];
        }
        __syncthreads();
    }

#pragma unroll
    for (int i = 0; i < TM; ++i) {
#pragma unroll
        for (int j = 0; j < TN; j += 4) {
            float4 o;
            o.x = acc[i][j + 0] * alpha;
            o.y = acc[i][j + 1] * alpha;
            o.z = acc[i][j + 2] * alpha;
            o.w = acc[i][j + 3] * alpha;
            *(float4*)(C + (size_t)(by * BM + ty * TM + i) * Nc + bx * BN + tx * TN + j) = o;
        }
    }
}

// ---------------------------------------------------------------------------
// Flash attention (fp32, online softmax, lazy rescale).
// grid: (L/BF, B*NH), block: BF=128 threads (one thread per query row).
// Streams K/V in 64x64 tiles through smem; inner reads are warp-broadcast LDS.
// ---------------------------------------------------------------------------
__global__ void __launch_bounds__(128, 3)
flash_attn_kernel(const float* __restrict__ q, const float* __restrict__ k,
                  const float* __restrict__ v, float* __restrict__ o)
{
    constexpr int BF = 128, BT = 64;
    __shared__ float Ks[BT][HD];
    __shared__ float Vs[BT][HD];

    const int tid = threadIdx.x;
    const int bn  = blockIdx.y;
    const int b   = bn >> 4;
    const int n   = bn & 15;
    const int frow = blockIdx.x * BF + tid;

    const size_t head_stride = (size_t)NH * HD;  // 1024
    const float* qp = q + ((size_t)(b * L_SEQ + frow) * NH + n) * HD;

    float qreg[HD];
#pragma unroll
    for (int h = 0; h < HD; h += 4) {
        float4 t = *(const float4*)(qp + h);
        qreg[h] = t.x; qreg[h + 1] = t.y; qreg[h + 2] = t.z; qreg[h + 3] = t.w;
    }

    float acc[HD];
#pragma unroll
    for (int h = 0; h < HD; ++h) acc[h] = 0.f;
    float m = -CUDART_INF_F;
    float l = 0.f;

    const float* kbase = k + ((size_t)(b * L_SEQ) * NH + n) * HD;
    const float* vbase = v + ((size_t)(b * L_SEQ) * NH + n) * HD;

    for (int t0 = 0; t0 < L_SEQ; t0 += BT) {
        // cooperative tile load: 64 rows x 64 floats for K and V
        for (int idx = tid; idx < BT * (HD / 4); idx += BF) {
            int r = idx / (HD / 4);
            int c = (idx % (HD / 4)) * 4;
            *(float4*)(&Ks[r][c]) = *(const float4*)(kbase + (size_t)(t0 + r) * head_stride + c);
            *(float4*)(&Vs[r][c]) = *(const float4*)(vbase + (size_t)(t0 + r) * head_stride + c);
        }
        __syncthreads();

        for (int j = 0; j < BT; ++j) {
            float s = 0.f;
#pragma unroll
            for (int h = 0; h < HD; h += 4) {
                float4 kk = *(const float4*)(&Ks[j][h]);
                s += qreg[h] * kk.x + qreg[h + 1] * kk.y
                   + qreg[h + 2] * kk.z + qreg[h + 3] * kk.w;
            }
            if (s > m) {                       // rare after warm-up (~log T times)
                float corr = __expf(m - s);    // expf(-inf) = 0 handles first key
                l *= corr;
#pragma unroll
                for (int h = 0; h < HD; ++h) acc[h] *= corr;
                m = s;
            }
            float p = __expf(s - m);
            l += p;
#pragma unroll
            for (int h = 0; h < HD; h += 4) {
                float4 vv = *(const float4*)(&Vs[j][h]);
                acc[h + 0] += p * vv.x;
                acc[h + 1] += p * vv.y;
                acc[h + 2] += p * vv.z;
                acc[h + 3] += p * vv.w;
            }
        }
        __syncthreads();
    }

    const float inv = 1.f / l;
    float* op = o + ((size_t)(b * L_SEQ + frow) * NH + n) * HD;
#pragma unroll
    for (int h = 0; h < HD; h += 4) {
        float4 t;
        t.x = acc[h + 0] * inv;
        t.y = acc[h + 1] * inv;
        t.z = acc[h + 2] * inv;
        t.w = acc[h + 3] * inv;
        *(float4*)(op + h) = t;
    }
}

// ---------------------------------------------------------------------------
// kernel_launch
// inputs: [0]=query_input [1]=key_input [2]=value_input [3]=Wq [4]=Wk [5]=Wv [6]=Wo
// ---------------------------------------------------------------------------
extern "C" void kernel_launch(void* const* d_in, const int* in_sizes, int n_in,
                              void* d_out, int out_size)
{
    const float* qin = (const float*)d_in[0];
    const float* kin = (const float*)d_in[1];
    const float* vin = (const float*)d_in[2];
    const float* Wq  = (const float*)d_in[3];
    const float* Wk  = (const float*)d_in[4];
    const float* Wv  = (const float*)d_in[5];
    const float* Wo  = (const float*)d_in[6];
    float* out = (float*)d_out;

    float *dq, *dk, *dv, *dattn;
    cudaGetSymbolAddress((void**)&dq,    g_q);
    cudaGetSymbolAddress((void**)&dk,    g_k);
    cudaGetSymbolAddress((void**)&dv,    g_v);
    cudaGetSymbolAddress((void**)&dattn, g_attn);

    constexpr int BM = 128, BN = 128;
    dim3 block(256);
    dim3 grid_qkv(D_MOD / BN, M_ROWS / BM, 3);
    dim3 grid_o(D_MOD / BN, M_ROWS / BM, 1);

    // 1) fused QKV projections (q scaled by H^-0.5)
    GemmTriple qkv;
    qkv.A[0] = qin; qkv.A[1] = kin; qkv.A[2] = vin;
    qkv.W[0] = Wq;  qkv.W[1] = Wk;  qkv.W[2] = Wv;
    qkv.C[0] = dq;  qkv.C[1] = dk;  qkv.C[2] = dv;
    qkv.alpha[0] = 0.125f;  // 64^-0.5
    qkv.alpha[1] = 1.f;
    qkv.alpha[2] = 1.f;
    sgemm_kernel<3><<<grid_qkv, block>>>(qkv, M_ROWS, D_MOD, D_MOD);

    // 2) flash attention
    dim3 agrid(L_SEQ / 128, B_SZ * NH);
    flash_attn_kernel<<<agrid, 128>>>(dq, dk, dv, dattn);

    // 3) output projection
    GemmTriple og;
    og.A[0] = dattn; og.W[0] = Wo; og.C[0] = out; og.alpha[0] = 1.f;
    og.A[1] = og.A[2] = nullptr; og.W[1] = og.W[2] = nullptr;
    og.C[1] = og.C[2] = nullptr; og.alpha[1] = og.alpha[2] = 0.f;
    sgemm_kernel<1><<<grid_o, block>>>(og, M_ROWS, D_MOD, D_MOD);
}

// round 2
// speedup vs baseline: 3.4559x; 3.4559x over previous
#include <cuda_runtime.h>
#include <math_constants.h>
#include <cstdint>

// Problem constants
#define B_SZ   2
#define L_SEQ  2048
#define D_MOD  1024
#define NH     16
#define HD     64
#define M_ROWS (B_SZ * L_SEQ)   // 4096

// Scratch (allocation-free rule: __device__ globals)
__device__ float g_q[M_ROWS * D_MOD];
__device__ float g_k[M_ROWS * D_MOD];
__device__ float g_v[M_ROWS * D_MOD];
__device__ float g_attn[M_ROWS * D_MOD];

// ---------------------------------------------------------------------------
// tf32 helpers
// ---------------------------------------------------------------------------
__device__ __forceinline__ float tf32r(float x) {
    uint32_t u;
    asm("cvt.rna.tf32.f32 %0, %1;" : "=r"(u) : "f"(x));
    return __uint_as_float(u);
}

__device__ __forceinline__ void mma_tf32(float c[4],
                                         float a0, float a1, float a2, float a3,
                                         float b0, float b1)
{
    asm volatile(
        "mma.sync.aligned.m16n8k8.row.col.f32.tf32.tf32.f32 "
        "{%0,%1,%2,%3},{%4,%5,%6,%7},{%8,%9},{%0,%1,%2,%3};"
        : "+f"(c[0]), "+f"(c[1]), "+f"(c[2]), "+f"(c[3])
        : "r"(__float_as_uint(a0)), "r"(__float_as_uint(a1)),
          "r"(__float_as_uint(a2)), "r"(__float_as_uint(a3)),
          "r"(__float_as_uint(b0)), "r"(__float_as_uint(b1)));
}

// ---------------------------------------------------------------------------
// tf32 tensor-core GEMM: C[M,Nc] = alpha * A[M,K] @ W[K,Nc]  (both row-major)
// BM=128, BN=128, BK=16; 8 warps in 2x4 grid, each warp 64x32 via m16n8k8.
// ---------------------------------------------------------------------------
struct GemmTriple {
    const float* A[3];
    const float* W[3];
    float*       C[3];
    float        alpha[3];
};

template <int NZ>
__global__ void __launch_bounds__(256)
mma_gemm(GemmTriple args, int M, int Nc, int K)
{
    constexpr int SA = 136;   // smem row stride (floats); 136%32==8 -> conflict-free frags
    __shared__ float As[16 * SA];  // [k][m]
    __shared__ float Ws[16 * SA];  // [k][n]

    const int z = (NZ > 1) ? blockIdx.z : 0;
    const float* __restrict__ A = args.A[z];
    const float* __restrict__ W = args.W[z];
    float* __restrict__ C = args.C[z];
    const float alpha = args.alpha[z];

    const int tid  = threadIdx.x;
    const int lane = tid & 31;
    const int w    = tid >> 5;
    const int g    = lane >> 2;   // 0..7
    const int tig  = lane & 3;    // 0..3
    const int warp_m = w >> 2;    // 0..1
    const int warp_n = w & 3;     // 0..3
    const int mbase = warp_m * 64;
    const int nbase = warp_n * 32;
    const int bx = blockIdx.x, by = blockIdx.y;

    // A load mapping: row = tid&63 (+64), colquad = tid>>6 (consecutive lanes -> consecutive rows)
    const int ar = tid & 63;
    const int acq = tid >> 6;     // 0..3
    // W load mapping: row = tid>>5 (+8), col = (tid&31)*4 (coalesced)
    const int wr = tid >> 5;      // 0..7
    const int wc = (tid & 31) * 4;

    const float* Ap = A + (size_t)(by * 128 + ar) * K + acq * 4;
    const float* Wp = W + (size_t)wr * Nc + bx * 128 + wc;

    float acc[4][4][4];
#pragma unroll
    for (int mt = 0; mt < 4; ++mt)
#pragma unroll
        for (int nt = 0; nt < 4; ++nt)
#pragma unroll
            for (int i = 0; i < 4; ++i) acc[mt][nt][i] = 0.f;

    float4 a0r, a1r, w0r, w1r;

    auto ldtile = [&](int k0) {
        a0r = *(const float4*)(Ap + k0);
        a1r = *(const float4*)(Ap + (size_t)64 * K + k0);
        w0r = *(const float4*)(Wp + (size_t)k0 * Nc);
        w1r = *(const float4*)(Wp + (size_t)(k0 + 8) * Nc);
    };
    auto sttile = [&]() {
        As[(acq * 4 + 0) * SA + ar] = tf32r(a0r.x);
        As[(acq * 4 + 1) * SA + ar] = tf32r(a0r.y);
        As[(acq * 4 + 2) * SA + ar] = tf32r(a0r.z);
        As[(acq * 4 + 3) * SA + ar] = tf32r(a0r.w);
        As[(acq * 4 + 0) * SA + ar + 64] = tf32r(a1r.x);
        As[(acq * 4 + 1) * SA + ar + 64] = tf32r(a1r.y);
        As[(acq * 4 + 2) * SA + ar + 64] = tf32r(a1r.z);
        As[(acq * 4 + 3) * SA + ar + 64] = tf32r(a1r.w);
        Ws[wr * SA + wc + 0] = tf32r(w0r.x);
        Ws[wr * SA + wc + 1] = tf32r(w0r.y);
        Ws[wr * SA + wc + 2] = tf32r(w0r.z);
        Ws[wr * SA + wc + 3] = tf32r(w0r.w);
        Ws[(wr + 8) * SA + wc + 0] = tf32r(w1r.x);
        Ws[(wr + 8) * SA + wc + 1] = tf32r(w1r.y);
        Ws[(wr + 8) * SA + wc + 2] = tf32r(w1r.z);
        Ws[(wr + 8) * SA + wc + 3] = tf32r(w1r.w);
    };

    ldtile(0);
    sttile();
    __syncthreads();

    for (int k0 = 0; k0 < K; k0 += 16) {
        const bool more = (k0 + 16) < K;
        if (more) ldtile(k0 + 16);

#pragma unroll
        for (int ks = 0; ks < 2; ++ks) {
            float af[4][4], bf[4][2];
            const int kr = ks * 8 + tig;
#pragma unroll
            for (int mt = 0; mt < 4; ++mt) {
                const int m = mbase + mt * 16 + g;
                af[mt][0] = As[kr * SA + m];
                af[mt][1] = As[kr * SA + m + 8];
                af[mt][2] = As[(kr + 4) * SA + m];
                af[mt][3] = As[(kr + 4) * SA + m + 8];
            }
#pragma unroll
            for (int nt = 0; nt < 4; ++nt) {
                const int n = nbase + nt * 8 + g;
                bf[nt][0] = Ws[kr * SA + n];
                bf[nt][1] = Ws[(kr + 4) * SA + n];
            }
#pragma unroll
            for (int mt = 0; mt < 4; ++mt)
#pragma unroll
                for (int nt = 0; nt < 4; ++nt)
                    mma_tf32(acc[mt][nt], af[mt][0], af[mt][1], af[mt][2], af[mt][3],
                             bf[nt][0], bf[nt][1]);
        }
        __syncthreads();
        if (more) { sttile(); __syncthreads(); }
    }

    // epilogue
#pragma unroll
    for (int mt = 0; mt < 4; ++mt) {
        const int row0 = by * 128 + mbase + mt * 16 + g;
#pragma unroll
        for (int nt = 0; nt < 4; ++nt) {
            const int col = bx * 128 + nbase + nt * 8 + tig * 2;
            float2 lo = make_float2(acc[mt][nt][0] * alpha, acc[mt][nt][1] * alpha);
            float2 hi = make_float2(acc[mt][nt][2] * alpha, acc[mt][nt][3] * alpha);
            *(float2*)(C + (size_t)row0 * Nc + col) = lo;
            *(float2*)(C + (size_t)(row0 + 8) * Nc + col) = hi;
        }
    }
}

// ---------------------------------------------------------------------------
// Tensor-core flash attention (tf32 mma, fp32 accum, online softmax).
// grid: (L/64, B*NH), block 128 (4 warps; warp w owns query rows 16w..16w+15).
// smem: buf0 (64x68) holds Q, then K, then P (aliased); buf1 (64x72) holds V.
// ---------------------------------------------------------------------------
#define KS_STRIDE 68   // 68%32==4 -> frag reads bank = 4g+tig (distinct)
#define VS_STRIDE 72   // 72%32==8 -> frag reads bank = 8tig+g (distinct)

__global__ void __launch_bounds__(128)
flash_mma(const float* __restrict__ q, const float* __restrict__ k,
          const float* __restrict__ v, float* __restrict__ o)
{
    __shared__ float buf0[64 * KS_STRIDE];  // Q -> K -> P
    __shared__ float buf1[64 * VS_STRIDE];  // V

    const int tid  = threadIdx.x;
    const int lane = tid & 31;
    const int w    = tid >> 5;
    const int g    = lane >> 2;
    const int tig  = lane & 3;

    const int bn = blockIdx.y;
    const int b  = bn >> 4;
    const int n  = bn & 15;
    const int f0 = blockIdx.x * 64;

    const float* qbase = q + (size_t)b * L_SEQ * D_MOD + (size_t)n * HD;
    const float* kbase = k + (size_t)b * L_SEQ * D_MOD + (size_t)n * HD;
    const float* vbase = v + (size_t)b * L_SEQ * D_MOD + (size_t)n * HD;

    // ---- load Q tile (64x64) into buf0 with tf32 rounding
    for (int i = tid; i < 64 * 16; i += 128) {
        const int r = i >> 4;
        const int c = (i & 15) * 4;
        float4 t = *(const float4*)(qbase + (size_t)(f0 + r) * D_MOD + c);
        buf0[r * KS_STRIDE + c + 0] = tf32r(t.x);
        buf0[r * KS_STRIDE + c + 1] = tf32r(t.y);
        buf0[r * KS_STRIDE + c + 2] = tf32r(t.z);
        buf0[r * KS_STRIDE + c + 3] = tf32r(t.w);
    }
    __syncthreads();

    // ---- extract Q A-fragments (rows 16w+g, 16w+g+8; 8 k-steps)
    float qa[8][4];
    const int qr = 16 * w + g;
#pragma unroll
    for (int ks = 0; ks < 8; ++ks) {
        const int c = ks * 8 + tig;
        qa[ks][0] = buf0[qr * KS_STRIDE + c];
        qa[ks][1] = buf0[(qr + 8) * KS_STRIDE + c];
        qa[ks][2] = buf0[qr * KS_STRIDE + c + 4];
        qa[ks][3] = buf0[(qr + 8) * KS_STRIDE + c + 4];
    }
    __syncthreads();

    float oacc[8][4];
#pragma unroll
    for (int nt = 0; nt < 8; ++nt)
#pragma unroll
        for (int i = 0; i < 4; ++i) oacc[nt][i] = 0.f;
    float m0 = -CUDART_INF_F, m1 = -CUDART_INF_F;
    float l0 = 0.f, l1 = 0.f;

    for (int t0 = 0; t0 < L_SEQ; t0 += 64) {
        // ---- load K,V tiles
        for (int i = tid; i < 64 * 16; i += 128) {
            const int r = i >> 4;
            const int c = (i & 15) * 4;
            float4 tk = *(const float4*)(kbase + (size_t)(t0 + r) * D_MOD + c);
            float4 tv = *(const float4*)(vbase + (size_t)(t0 + r) * D_MOD + c);
            buf0[r * KS_STRIDE + c + 0] = tf32r(tk.x);
            buf0[r * KS_STRIDE + c + 1] = tf32r(tk.y);
            buf0[r * KS_STRIDE + c + 2] = tf32r(tk.z);
            buf0[r * KS_STRIDE + c + 3] = tf32r(tk.w);
            buf1[r * VS_STRIDE + c + 0] = tf32r(tv.x);
            buf1[r * VS_STRIDE + c + 1] = tf32r(tv.y);
            buf1[r * VS_STRIDE + c + 2] = tf32r(tv.z);
            buf1[r * VS_STRIDE + c + 3] = tf32r(tv.w);
        }
        __syncthreads();

        // ---- S = Q @ K^T   (S[f,t], 16x64 per warp)
        float sacc[8][4];
#pragma unroll
        for (int nt = 0; nt < 8; ++nt)
#pragma unroll
            for (int i = 0; i < 4; ++i) sacc[nt][i] = 0.f;

#pragma unroll
        for (int nt = 0; nt < 8; ++nt) {
            const int trow = nt * 8 + g;
#pragma unroll
            for (int ks = 0; ks < 8; ++ks) {
                const float b0 = buf0[trow * KS_STRIDE + ks * 8 + tig];
                const float b1 = buf0[trow * KS_STRIDE + ks * 8 + tig + 4];
                mma_tf32(sacc[nt], qa[ks][0], qa[ks][1], qa[ks][2], qa[ks][3], b0, b1);
            }
        }
        __syncthreads();   // all warps done reading K before P overwrites buf0

        // ---- online softmax on S fragments
        float tm0 = -CUDART_INF_F, tm1 = -CUDART_INF_F;
#pragma unroll
        for (int nt = 0; nt < 8; ++nt) {
            tm0 = fmaxf(tm0, fmaxf(sacc[nt][0], sacc[nt][1]));
            tm1 = fmaxf(tm1, fmaxf(sacc[nt][2], sacc[nt][3]));
        }
        tm0 = fmaxf(tm0, __shfl_xor_sync(0xffffffffu, tm0, 1));
        tm0 = fmaxf(tm0, __shfl_xor_sync(0xffffffffu, tm0, 2));
        tm1 = fmaxf(tm1, __shfl_xor_sync(0xffffffffu, tm1, 1));
        tm1 = fmaxf(tm1, __shfl_xor_sync(0xffffffffu, tm1, 2));

        const float nm0 = fmaxf(m0, tm0);
        const float nm1 = fmaxf(m1, tm1);
        const float sc0 = __expf(m0 - nm0);
        const float sc1 = __expf(m1 - nm1);
        m0 = nm0; m1 = nm1;
        l0 *= sc0; l1 *= sc1;
#pragma unroll
        for (int nt = 0; nt < 8; ++nt) {
            oacc[nt][0] *= sc0; oacc[nt][1] *= sc0;
            oacc[nt][2] *= sc1; oacc[nt][3] *= sc1;
        }

        float rs0 = 0.f, rs1 = 0.f;
#pragma unroll
        for (int nt = 0; nt < 8; ++nt) {
            const float p0 = __expf(sacc[nt][0] - m0);
            const float p1 = __expf(sacc[nt][1] - m0);
            const float p2 = __expf(sacc[nt][2] - m1);
            const float p3 = __expf(sacc[nt][3] - m1);
            rs0 += p0 + p1;
            rs1 += p2 + p3;
            const int col = nt * 8 + tig * 2;
            buf0[qr * KS_STRIDE + col]           = tf32r(p0);
            buf0[qr * KS_STRIDE + col + 1]       = tf32r(p1);
            buf0[(qr + 8) * KS_STRIDE + col]     = tf32r(p2);
            buf0[(qr + 8) * KS_STRIDE + col + 1] = tf32r(p3);
        }
        rs0 += __shfl_xor_sync(0xffffffffu, rs0, 1);
        rs0 += __shfl_xor_sync(0xffffffffu, rs0, 2);
        rs1 += __shfl_xor_sync(0xffffffffu, rs1, 1);
        rs1 += __shfl_xor_sync(0xffffffffu, rs1, 2);
        l0 += rs0; l1 += rs1;
        __syncwarp();   // P rows are warp-private; warp-level ordering is enough

        // ---- O += P @ V   (A = P from buf0, B = V from buf1)
#pragma unroll
        for (int kt = 0; kt < 8; ++kt) {
            const int c = kt * 8 + tig;
            const float pa0 = buf0[qr * KS_STRIDE + c];
            const float pa1 = buf0[(qr + 8) * KS_STRIDE + c];
            const float pa2 = buf0[qr * KS_STRIDE + c + 4];
            const float pa3 = buf0[(qr + 8) * KS_STRIDE + c + 4];
#pragma unroll
            for (int nt = 0; nt < 8; ++nt) {
                const float b0 = buf1[(kt * 8 + tig) * VS_STRIDE + nt * 8 + g];
                const float b1 = buf1[(kt * 8 + tig + 4) * VS_STRIDE + nt * 8 + g];
                mma_tf32(oacc[nt], pa0, pa1, pa2, pa3, b0, b1);
            }
        }
        __syncthreads();   // all warps done with P/V before next tile load
    }

    // ---- epilogue: O /= l, write to g_attn
    const float inv0 = 1.f / l0;
    const float inv1 = 1.f / l1;
    float* ob = o + (size_t)(b * L_SEQ + f0 + qr) * D_MOD + (size_t)n * HD;
#pragma unroll
    for (int nt = 0; nt < 8; ++nt) {
        const int col = nt * 8 + tig * 2;
        float2 lo = make_float2(oacc[nt][0] * inv0, oacc[nt][1] * inv0);
        float2 hi = make_float2(oacc[nt][2] * inv1, oacc[nt][3] * inv1);
        *(float2*)(ob + col) = lo;
        *(float2*)(ob + (size_t)8 * D_MOD + col) = hi;
    }
}

// ---------------------------------------------------------------------------
// kernel_launch
// inputs: [0]=query [1]=key [2]=value [3]=Wq [4]=Wk [5]=Wv [6]=Wo
// ---------------------------------------------------------------------------
extern "C" void kernel_launch(void* const* d_in, const int* in_sizes, int n_in,
                              void* d_out, int out_size)
{
    const float* qin = (const float*)d_in[0];
    const float* kin = (const float*)d_in[1];
    const float* vin = (const float*)d_in[2];
    const float* Wq  = (const float*)d_in[3];
    const float* Wk  = (const float*)d_in[4];
    const float* Wv  = (const float*)d_in[5];
    const float* Wo  = (const float*)d_in[6];
    float* out = (float*)d_out;

    float *dq, *dk, *dv, *dattn;
    cudaGetSymbolAddress((void**)&dq,    g_q);
    cudaGetSymbolAddress((void**)&dk,    g_k);
    cudaGetSymbolAddress((void**)&dv,    g_v);
    cudaGetSymbolAddress((void**)&dattn, g_attn);

    dim3 block(256);
    dim3 grid_qkv(D_MOD / 128, M_ROWS / 128, 3);
    dim3 grid_o(D_MOD / 128, M_ROWS / 128, 1);

    // 1) fused QKV projections (q scaled by 64^-0.5)
    GemmTriple qkv;
    qkv.A[0] = qin; qkv.A[1] = kin; qkv.A[2] = vin;
    qkv.W[0] = Wq;  qkv.W[1] = Wk;  qkv.W[2] = Wv;
    qkv.C[0] = dq;  qkv.C[1] = dk;  qkv.C[2] = dv;
    qkv.alpha[0] = 0.125f;
    qkv.alpha[1] = 1.f;
    qkv.alpha[2] = 1.f;
    mma_gemm<3><<<grid_qkv, block>>>(qkv, M_ROWS, D_MOD, D_MOD);

    // 2) tensor-core flash attention
    dim3 agrid(L_SEQ / 64, B_SZ * NH);
    flash_mma<<<agrid, 128>>>(dq, dk, dv, dattn);

    // 3) output projection
    GemmTriple og;
    og.A[0] = dattn; og.W[0] = Wo; og.C[0] = out; og.alpha[0] = 1.f;
    og.A[1] = og.A[2] = nullptr; og.W[1] = og.W[2] = nullptr;
    og.C[1] = og.C[2] = nullptr; og.alpha[1] = og.alpha[2] = 0.f;
    mma_gemm<1><<<grid_o, block>>>(og, M_ROWS, D_MOD, D_MOD);
}